// round 15
// baseline (speedup 1.0000x reference)
#include <cuda_runtime.h>
#include <cstdint>

// Problem constants (fixed by the dataset)
#define MAXN 100000
#define MAXE 600000
#define DF   128            // feature dim (in == hid == 128)

// ---------------------------------------------------------------------------
// Scratch (no allocations allowed -> __device__ globals)
// ---------------------------------------------------------------------------
__device__ float g_y[(size_t)MAXN * DF];    // y = z_pre * dinv[row]  (GEMM output)
__device__ float g_agg[(size_t)MAXN * DF];  // S = y[i] + sum_{j->i} y[j]
__device__ int   g_deg[MAXN];
__device__ float g_dinv[MAXN];
// CSR (by destination node)
__device__ int   g_csr_src[MAXE];
__device__ int   g_off[MAXN + 1];
__device__ int   g_cur[MAXN];
__device__ int   g_bsum[128];
__device__ int   g_boff[128];

// ---------------------------------------------------------------------------
// Degree / normalization
// ---------------------------------------------------------------------------
__global__ void deg_init_kernel(int n) {
    int i = blockIdx.x * blockDim.x + threadIdx.x;
    if (i < n) g_deg[i] = 1;   // self-loop
}

__global__ void deg_count_kernel(const int* __restrict__ dst, int E) {
    int e = blockIdx.x * blockDim.x + threadIdx.x;
    if (e < E) atomicAdd(&g_deg[dst[e]], 1);
}

__global__ void dinv_kernel(int n) {
    int i = blockIdx.x * blockDim.x + threadIdx.x;
    if (i < n) g_dinv[i] = rsqrtf((float)g_deg[i]);
}

// ---------------------------------------------------------------------------
// CSR build: exclusive scan of cnt[i] = deg[i]-1 (in-edge count), then bucket
// fill. 3-kernel exact scan (block scan -> scan of block sums -> add offsets).
// ---------------------------------------------------------------------------
static constexpr int SCAN_B  = 1024;
static constexpr int SCAN_NB = (MAXN + SCAN_B - 1) / SCAN_B;   // 98

__global__ void scanA_kernel(int n) {
    __shared__ int sh[SCAN_B];
    int t = threadIdx.x, b = blockIdx.x;
    int i = b * SCAN_B + t;
    int v = (i < n) ? (g_deg[i] - 1) : 0;
    sh[t] = v;
    __syncthreads();
    #pragma unroll
    for (int o = 1; o < SCAN_B; o <<= 1) {
        int x = (t >= o) ? sh[t - o] : 0;
        __syncthreads();
        sh[t] += x;
        __syncthreads();
    }
    int incl = sh[t];
    if (i <= n) g_off[i] = incl - v;           // exclusive, pre-block-offset
    if (t == SCAN_B - 1) g_bsum[b] = incl;     // block total
}

__global__ void scanB_kernel(int nb) {
    __shared__ int sh[128];
    int t = threadIdx.x;
    sh[t] = (t < nb) ? g_bsum[t] : 0;
    __syncthreads();
    if (t == 0) {
        int run = 0;
        for (int b = 0; b < nb; b++) { int x = sh[b]; sh[b] = run; run += x; }
    }
    __syncthreads();
    if (t < nb) g_boff[t] = sh[t];
}

__global__ void scanC_kernel(int n) {
    int t = threadIdx.x, b = blockIdx.x;
    int i = b * SCAN_B + t;
    if (i <= n) {
        int o = g_off[i] + g_boff[b];
        g_off[i] = o;
        if (i < n) g_cur[i] = o;
    }
}

__global__ void csr_fill_kernel(const int* __restrict__ src,
                                const int* __restrict__ dst, int E) {
    int e = blockIdx.x * blockDim.x + threadIdx.x;
    if (e >= E) return;
    int s = src[e], d = dst[e];
    int pos = atomicAdd(&g_cur[d], 1);
    g_csr_src[pos] = s;
}

// ---------------------------------------------------------------------------
// Fused GEMM:  y = act(A) @ W * dinv[row]
//   ASRC = 0 : A = Aext (external input x)
//   ASRC = 1 : A[i][k] = relu(g_agg[i][k] * dinv[i] + preBias[k])
//              (g_agg holds raw sums S from the gather; the dinv factor of
//               the previous layer's aggregation is folded in here)
// Epilogue writes ONLY g_y = acc * dinv[row] (self-loop + symmetric norm
// pre-factored; the consumer applies the remaining dinv).
// Tile: 128x128 per block, K steps of 16, 256 threads, 8x8 per thread.
// ---------------------------------------------------------------------------
template<int ASRC, bool PRERELU>
__global__ void __launch_bounds__(256)
gemm_fused_kernel(const float* __restrict__ Aext,
                  const float* __restrict__ W,
                  const float* __restrict__ preBias,
                  int M)
{
    const int BM = 128, BK = 16;
    __shared__ float As[BK][BM];   // [k][m]
    __shared__ float Bs[BK][BM];   // [k][n]

    const float* A = (ASRC == 0) ? Aext : g_agg;

    int tid = threadIdx.x;
    int tx  = tid & 15;        // col group (8 cols each)
    int ty  = tid >> 4;        // row group (8 rows each)
    int rowBase = blockIdx.x * BM;

    float acc[8][8];
    #pragma unroll
    for (int i = 0; i < 8; i++)
        #pragma unroll
        for (int j = 0; j < 8; j++) acc[i][j] = 0.0f;

    for (int k0 = 0; k0 < DF; k0 += BK) {
        // --- load A tile: 128 rows x 16 k (512 float4, 2 per thread) ---
        #pragma unroll
        for (int it = 0; it < 2; ++it) {
            int q  = tid + it * 256;
            int r  = q >> 2;             // row within tile
            int kk = (q & 3) << 2;       // 0,4,8,12
            int grow = rowBase + r;
            float4 v = make_float4(0.f, 0.f, 0.f, 0.f);
            if (grow < M)
                v = *(const float4*)(A + (size_t)grow * DF + k0 + kk);
            if (PRERELU) {
                float di = g_dinv[grow < M ? grow : 0];
                float4 bb = *(const float4*)(preBias + k0 + kk);
                v.x = fmaxf(fmaf(v.x, di, bb.x), 0.f);
                v.y = fmaxf(fmaf(v.y, di, bb.y), 0.f);
                v.z = fmaxf(fmaf(v.z, di, bb.z), 0.f);
                v.w = fmaxf(fmaf(v.w, di, bb.w), 0.f);
                if (grow >= M) { v.x = v.y = v.z = v.w = 0.f; }
            }
            As[kk + 0][r] = v.x;
            As[kk + 1][r] = v.y;
            As[kk + 2][r] = v.z;
            As[kk + 3][r] = v.w;
        }
        // --- load W tile: 16 k-rows x 128 cols ---
        #pragma unroll
        for (int it = 0; it < 2; ++it) {
            int q = tid + it * 256;
            int r = q >> 5;              // 0..15
            int c = (q & 31) << 2;       // 0..124
            *(float4*)(&Bs[r][c]) = *(const float4*)(W + (size_t)(k0 + r) * DF + c);
        }
        __syncthreads();

        #pragma unroll
        for (int kk = 0; kk < BK; ++kk) {
            float ra[8], rb[8];
            #pragma unroll
            for (int i = 0; i < 8; i++) ra[i] = As[kk][ty * 8 + i];
            #pragma unroll
            for (int j = 0; j < 8; j++) rb[j] = Bs[kk][tx * 8 + j];
            #pragma unroll
            for (int i = 0; i < 8; i++)
                #pragma unroll
                for (int j = 0; j < 8; j++)
                    acc[i][j] = fmaf(ra[i], rb[j], acc[i][j]);
        }
        __syncthreads();
    }

    // --- epilogue: y = acc * dinv[row] (single-array store) ---
    #pragma unroll
    for (int i = 0; i < 8; i++) {
        int grow = rowBase + ty * 8 + i;
        if (grow >= M) continue;
        float di = g_dinv[grow];
        size_t base = (size_t)grow * DF + tx * 8;
        #pragma unroll
        for (int j = 0; j < 8; j += 4) {
            float4 v = make_float4(acc[i][j] * di, acc[i][j + 1] * di,
                                   acc[i][j + 2] * di, acc[i][j + 3] * di);
            *(float4*)(g_y + base + j) = v;
        }
    }
}

// ---------------------------------------------------------------------------
// CSR gather aggregation: warp per node.
//   S[i] = y[i] + sum_{e in in(i)} y[src[e]]        (no atomics, streaming out)
// ---------------------------------------------------------------------------
__global__ void gather_kernel(int N)
{
    int node = (blockIdx.x * blockDim.x + threadIdx.x) >> 5;
    int lane = threadIdx.x & 31;
    if (node >= N) return;
    int beg = g_off[node];
    int end = g_off[node + 1];
    float4 acc = ((const float4*)(g_y + (size_t)node * DF))[lane];   // self term
    for (int e = beg; e < end; e++) {
        int s = g_csr_src[e];
        float4 v = ((const float4*)(g_y + (size_t)s * DF))[lane];
        acc.x += v.x; acc.y += v.y; acc.z += v.z; acc.w += v.w;
    }
    ((float4*)(g_agg + (size_t)node * DF))[lane] = acc;
}

// ---------------------------------------------------------------------------
// Edge decode: z2[i] = S2[i]*dinv[i] + b2;  out[e] = <z2[src], z2[dst]>
// ---------------------------------------------------------------------------
__global__ void edge_dot_kernel(const int* __restrict__ src,
                                const int* __restrict__ dst,
                                const float* __restrict__ bias,
                                float* __restrict__ out,
                                int E)
{
    int warp = (blockIdx.x * blockDim.x + threadIdx.x) >> 5;
    int lane = threadIdx.x & 31;
    if (warp >= E) return;
    int s = __ldg(src + warp);
    int d = __ldg(dst + warp);
    float ds = g_dinv[s];
    float dd = g_dinv[d];
    float4 bb = *(const float4*)(bias + lane * 4);
    float4 a  = *(const float4*)(g_agg + (size_t)s * DF + lane * 4);
    float4 b  = *(const float4*)(g_agg + (size_t)d * DF + lane * 4);
    float p = fmaf(a.x, ds, bb.x) * fmaf(b.x, dd, bb.x)
            + fmaf(a.y, ds, bb.y) * fmaf(b.y, dd, bb.y)
            + fmaf(a.z, ds, bb.z) * fmaf(b.z, dd, bb.z)
            + fmaf(a.w, ds, bb.w) * fmaf(b.w, dd, bb.w);
    #pragma unroll
    for (int o = 16; o > 0; o >>= 1)
        p += __shfl_xor_sync(0xffffffffu, p, o);
    if (lane == 0) out[warp] = p;
}

// ---------------------------------------------------------------------------
// kernel_launch
// Inputs (metadata order): x [N*128], edge_index [2*E], W1, b1, W2, b2
// ---------------------------------------------------------------------------
extern "C" void kernel_launch(void* const* d_in, const int* in_sizes, int n_in,
                              void* d_out, int out_size)
{
    const float* x  = (const float*)d_in[0];
    const int*   ei = (const int*)  d_in[1];
    const float* W1 = (const float*)d_in[2];
    const float* b1 = (const float*)d_in[3];
    const float* W2 = (const float*)d_in[4];
    const float* b2 = (const float*)d_in[5];

    int E = in_sizes[1] / 2;
    int N = in_sizes[0] / DF;
    if (N > MAXN) N = MAXN;
    if (E > MAXE) E = MAXE;

    const int* src = ei;
    const int* dst = ei + E;
    float* out = (float*)d_out;

    const int T = 256;
    int nb = (N + SCAN_B - 1) / SCAN_B;

    // ---- degrees, normalization, CSR build ----
    deg_init_kernel<<<(N + T - 1) / T, T>>>(N);
    deg_count_kernel<<<(E + T - 1) / T, T>>>(dst, E);
    dinv_kernel<<<(N + T - 1) / T, T>>>(N);
    scanA_kernel<<<nb, SCAN_B>>>(N);
    scanB_kernel<<<1, 128>>>(nb);
    scanC_kernel<<<nb, SCAN_B>>>(N);
    csr_fill_kernel<<<(E + T - 1) / T, T>>>(src, dst, E);

    int gemm_blocks = (N + 127) / 128;
    int node_blocks = (N + 7) / 8;   // warp per node, 8 warps/block
    int edge_blocks = (E + 7) / 8;   // warp per edge

    // ---- Layer 1: y1 = (x @ W1) * dinv ; S1 = gather(y1) ----
    gemm_fused_kernel<0, false><<<gemm_blocks, T>>>(x, W1, nullptr, N);
    gather_kernel<<<node_blocks, T>>>(N);
    // g_agg = S1 (raw sums; dinv + b1 + relu applied in GEMM2's A-load)

    // ---- Layer 2: y2 = relu(S1*dinv + b1) @ W2 * dinv ; S2 = gather(y2) ----
    gemm_fused_kernel<1, true><<<gemm_blocks, T>>>(nullptr, W2, b1, N);
    gather_kernel<<<node_blocks, T>>>(N);
    // g_agg = S2 (dinv + b2 applied in decode)

    // ---- Decode: per-edge dot of endpoint embeddings ----
    edge_dot_kernel<<<edge_blocks, T>>>(src, dst, b2, out, E);
}

// round 16
// speedup vs baseline: 1.0005x; 1.0005x over previous
#include <cuda_runtime.h>
#include <cstdint>

// Problem constants (fixed by the dataset)
#define MAXN 100000
#define MAXE 600000
#define DF   128            // feature dim (in == hid == 128)

// ---------------------------------------------------------------------------
// Scratch (no allocations allowed -> __device__ globals)
// ---------------------------------------------------------------------------
__device__ float g_y[(size_t)MAXN * DF];    // y = z_pre * dinv[row]  (GEMM output)
__device__ float g_agg[(size_t)MAXN * DF];  // S = y[i] + sum_{j->i} y[j]
__device__ int   g_deg[MAXN];
__device__ float g_dinv[MAXN];
// CSR (by destination node)
__device__ int   g_csr_src[MAXE];
__device__ int   g_off[MAXN + 1];
__device__ int   g_cur[MAXN];
__device__ int   g_bsum[128];
__device__ int   g_boff[128];

// ---------------------------------------------------------------------------
// Degree / normalization
// ---------------------------------------------------------------------------
__global__ void deg_init_kernel(int n) {
    int i = blockIdx.x * blockDim.x + threadIdx.x;
    if (i < n) g_deg[i] = 1;   // self-loop
}

__global__ void deg_count_kernel(const int* __restrict__ dst, int E) {
    int e = blockIdx.x * blockDim.x + threadIdx.x;
    if (e < E) atomicAdd(&g_deg[dst[e]], 1);
}

__global__ void dinv_kernel(int n) {
    int i = blockIdx.x * blockDim.x + threadIdx.x;
    if (i < n) g_dinv[i] = rsqrtf((float)g_deg[i]);
}

// ---------------------------------------------------------------------------
// CSR build: exclusive scan of cnt[i] = deg[i]-1 (in-edge count), then bucket
// fill. 3-kernel exact scan (block scan -> scan of block sums -> add offsets).
// ---------------------------------------------------------------------------
static constexpr int SCAN_B  = 1024;
static constexpr int SCAN_NB = (MAXN + SCAN_B - 1) / SCAN_B;   // 98

__global__ void scanA_kernel(int n) {
    __shared__ int sh[SCAN_B];
    int t = threadIdx.x, b = blockIdx.x;
    int i = b * SCAN_B + t;
    int v = (i < n) ? (g_deg[i] - 1) : 0;
    sh[t] = v;
    __syncthreads();
    #pragma unroll
    for (int o = 1; o < SCAN_B; o <<= 1) {
        int x = (t >= o) ? sh[t - o] : 0;
        __syncthreads();
        sh[t] += x;
        __syncthreads();
    }
    int incl = sh[t];
    if (i <= n) g_off[i] = incl - v;           // exclusive, pre-block-offset
    if (t == SCAN_B - 1) g_bsum[b] = incl;     // block total
}

__global__ void scanB_kernel(int nb) {
    __shared__ int sh[128];
    int t = threadIdx.x;
    sh[t] = (t < nb) ? g_bsum[t] : 0;
    __syncthreads();
    if (t == 0) {
        int run = 0;
        for (int b = 0; b < nb; b++) { int x = sh[b]; sh[b] = run; run += x; }
    }
    __syncthreads();
    if (t < nb) g_boff[t] = sh[t];
}

__global__ void scanC_kernel(int n) {
    int t = threadIdx.x, b = blockIdx.x;
    int i = b * SCAN_B + t;
    if (i <= n) {
        int o = g_off[i] + g_boff[b];
        g_off[i] = o;
        if (i < n) g_cur[i] = o;
    }
}

__global__ void csr_fill_kernel(const int* __restrict__ src,
                                const int* __restrict__ dst, int E) {
    int e = blockIdx.x * blockDim.x + threadIdx.x;
    if (e >= E) return;
    int s = src[e], d = dst[e];
    int pos = atomicAdd(&g_cur[d], 1);
    g_csr_src[pos] = s;
}

// ---------------------------------------------------------------------------
// Fused GEMM:  y = act(A) @ W * dinv[row]
//   ASRC = 0 : A = Aext (external input x)
//   ASRC = 1 : A[i][k] = relu(g_agg[i][k] * dinv[i] + preBias[k])
//              (g_agg holds raw sums S from the gather; the dinv factor of
//               the previous layer's aggregation is folded in here)
// Epilogue writes ONLY g_y = acc * dinv[row] (self-loop + symmetric norm
// pre-factored; the consumer applies the remaining dinv).
// Tile: 128x128 per block, K steps of 16, 256 threads, 8x8 per thread.
// ---------------------------------------------------------------------------
template<int ASRC, bool PRERELU>
__global__ void __launch_bounds__(256)
gemm_fused_kernel(const float* __restrict__ Aext,
                  const float* __restrict__ W,
                  const float* __restrict__ preBias,
                  int M)
{
    const int BM = 128, BK = 16;
    __shared__ float As[BK][BM];   // [k][m]
    __shared__ float Bs[BK][BM];   // [k][n]

    const float* A = (ASRC == 0) ? Aext : g_agg;

    int tid = threadIdx.x;
    int tx  = tid & 15;        // col group (8 cols each)
    int ty  = tid >> 4;        // row group (8 rows each)
    int rowBase = blockIdx.x * BM;

    float acc[8][8];
    #pragma unroll
    for (int i = 0; i < 8; i++)
        #pragma unroll
        for (int j = 0; j < 8; j++) acc[i][j] = 0.0f;

    for (int k0 = 0; k0 < DF; k0 += BK) {
        // --- load A tile: 128 rows x 16 k (512 float4, 2 per thread) ---
        #pragma unroll
        for (int it = 0; it < 2; ++it) {
            int q  = tid + it * 256;
            int r  = q >> 2;             // row within tile
            int kk = (q & 3) << 2;       // 0,4,8,12
            int grow = rowBase + r;
            float4 v = make_float4(0.f, 0.f, 0.f, 0.f);
            if (grow < M)
                v = *(const float4*)(A + (size_t)grow * DF + k0 + kk);
            if (PRERELU) {
                float di = g_dinv[grow < M ? grow : 0];
                float4 bb = *(const float4*)(preBias + k0 + kk);
                v.x = fmaxf(fmaf(v.x, di, bb.x), 0.f);
                v.y = fmaxf(fmaf(v.y, di, bb.y), 0.f);
                v.z = fmaxf(fmaf(v.z, di, bb.z), 0.f);
                v.w = fmaxf(fmaf(v.w, di, bb.w), 0.f);
                if (grow >= M) { v.x = v.y = v.z = v.w = 0.f; }
            }
            As[kk + 0][r] = v.x;
            As[kk + 1][r] = v.y;
            As[kk + 2][r] = v.z;
            As[kk + 3][r] = v.w;
        }
        // --- load W tile: 16 k-rows x 128 cols ---
        #pragma unroll
        for (int it = 0; it < 2; ++it) {
            int q = tid + it * 256;
            int r = q >> 5;              // 0..15
            int c = (q & 31) << 2;       // 0..124
            *(float4*)(&Bs[r][c]) = *(const float4*)(W + (size_t)(k0 + r) * DF + c);
        }
        __syncthreads();

        #pragma unroll
        for (int kk = 0; kk < BK; ++kk) {
            float ra[8], rb[8];
            #pragma unroll
            for (int i = 0; i < 8; i++) ra[i] = As[kk][ty * 8 + i];
            #pragma unroll
            for (int j = 0; j < 8; j++) rb[j] = Bs[kk][tx * 8 + j];
            #pragma unroll
            for (int i = 0; i < 8; i++)
                #pragma unroll
                for (int j = 0; j < 8; j++)
                    acc[i][j] = fmaf(ra[i], rb[j], acc[i][j]);
        }
        __syncthreads();
    }

    // --- epilogue: y = acc * dinv[row] (single-array store) ---
    #pragma unroll
    for (int i = 0; i < 8; i++) {
        int grow = rowBase + ty * 8 + i;
        if (grow >= M) continue;
        float di = g_dinv[grow];
        size_t base = (size_t)grow * DF + tx * 8;
        #pragma unroll
        for (int j = 0; j < 8; j += 4) {
            float4 v = make_float4(acc[i][j] * di, acc[i][j + 1] * di,
                                   acc[i][j + 2] * di, acc[i][j + 3] * di);
            *(float4*)(g_y + base + j) = v;
        }
    }
}

// ---------------------------------------------------------------------------
// CSR gather aggregation: warp per node.
//   S[i] = y[i] + sum_{e in in(i)} y[src[e]]        (no atomics, streaming out)
// ---------------------------------------------------------------------------
__global__ void gather_kernel(int N)
{
    int node = (blockIdx.x * blockDim.x + threadIdx.x) >> 5;
    int lane = threadIdx.x & 31;
    if (node >= N) return;
    int beg = g_off[node];
    int end = g_off[node + 1];
    float4 acc = ((const float4*)(g_y + (size_t)node * DF))[lane];   // self term
    for (int e = beg; e < end; e++) {
        int s = g_csr_src[e];
        float4 v = ((const float4*)(g_y + (size_t)s * DF))[lane];
        acc.x += v.x; acc.y += v.y; acc.z += v.z; acc.w += v.w;
    }
    ((float4*)(g_agg + (size_t)node * DF))[lane] = acc;
}

// ---------------------------------------------------------------------------
// Edge decode: z2[i] = S2[i]*dinv[i] + b2;  out[e] = <z2[src], z2[dst]>
// ---------------------------------------------------------------------------
__global__ void edge_dot_kernel(const int* __restrict__ src,
                                const int* __restrict__ dst,
                                const float* __restrict__ bias,
                                float* __restrict__ out,
                                int E)
{
    int warp = (blockIdx.x * blockDim.x + threadIdx.x) >> 5;
    int lane = threadIdx.x & 31;
    if (warp >= E) return;
    int s = __ldg(src + warp);
    int d = __ldg(dst + warp);
    float ds = g_dinv[s];
    float dd = g_dinv[d];
    float4 bb = *(const float4*)(bias + lane * 4);
    float4 a  = *(const float4*)(g_agg + (size_t)s * DF + lane * 4);
    float4 b  = *(const float4*)(g_agg + (size_t)d * DF + lane * 4);
    float p = fmaf(a.x, ds, bb.x) * fmaf(b.x, dd, bb.x)
            + fmaf(a.y, ds, bb.y) * fmaf(b.y, dd, bb.y)
            + fmaf(a.z, ds, bb.z) * fmaf(b.z, dd, bb.z)
            + fmaf(a.w, ds, bb.w) * fmaf(b.w, dd, bb.w);
    #pragma unroll
    for (int o = 16; o > 0; o >>= 1)
        p += __shfl_xor_sync(0xffffffffu, p, o);
    if (lane == 0) out[warp] = p;
}

// ---------------------------------------------------------------------------
// kernel_launch
// Inputs (metadata order): x [N*128], edge_index [2*E], W1, b1, W2, b2
// ---------------------------------------------------------------------------
extern "C" void kernel_launch(void* const* d_in, const int* in_sizes, int n_in,
                              void* d_out, int out_size)
{
    const float* x  = (const float*)d_in[0];
    const int*   ei = (const int*)  d_in[1];
    const float* W1 = (const float*)d_in[2];
    const float* b1 = (const float*)d_in[3];
    const float* W2 = (const float*)d_in[4];
    const float* b2 = (const float*)d_in[5];

    int E = in_sizes[1] / 2;
    int N = in_sizes[0] / DF;
    if (N > MAXN) N = MAXN;
    if (E > MAXE) E = MAXE;

    const int* src = ei;
    const int* dst = ei + E;
    float* out = (float*)d_out;

    const int T = 256;
    int nb = (N + SCAN_B - 1) / SCAN_B;

    // ---- degrees, normalization, CSR build ----
    deg_init_kernel<<<(N + T - 1) / T, T>>>(N);
    deg_count_kernel<<<(E + T - 1) / T, T>>>(dst, E);
    dinv_kernel<<<(N + T - 1) / T, T>>>(N);
    scanA_kernel<<<nb, SCAN_B>>>(N);
    scanB_kernel<<<1, 128>>>(nb);
    scanC_kernel<<<nb, SCAN_B>>>(N);
    csr_fill_kernel<<<(E + T - 1) / T, T>>>(src, dst, E);

    int gemm_blocks = (N + 127) / 128;
    int node_blocks = (N + 7) / 8;   // warp per node, 8 warps/block
    int edge_blocks = (E + 7) / 8;   // warp per edge

    // ---- Layer 1: y1 = (x @ W1) * dinv ; S1 = gather(y1) ----
    gemm_fused_kernel<0, false><<<gemm_blocks, T>>>(x, W1, nullptr, N);
    gather_kernel<<<node_blocks, T>>>(N);
    // g_agg = S1 (raw sums; dinv + b1 + relu applied in GEMM2's A-load)

    // ---- Layer 2: y2 = relu(S1*dinv + b1) @ W2 * dinv ; S2 = gather(y2) ----
    gemm_fused_kernel<1, true><<<gemm_blocks, T>>>(nullptr, W2, b1, N);
    gather_kernel<<<node_blocks, T>>>(N);
    // g_agg = S2 (dinv + b2 applied in decode)

    // ---- Decode: per-edge dot of endpoint embeddings ----
    edge_dot_kernel<<<edge_blocks, T>>>(src, dst, b2, out, E);
}